// round 6
// baseline (speedup 1.0000x reference)
#include <cuda_runtime.h>
#include <math.h>
#include <stdint.h>

#define BDIM   2
#define LDIM   2048
#define DMODEL 1024
#define DINNER 2048
#define DSTATE 16
#define DTRANK 64
#define DCONV  4
#define NROWS  (BDIM * LDIM)          // 4096
#define XDBLW  (DTRANK + 2 * DSTATE)  // 96

// ---------------- f32 scratch ----------------
__device__ __align__(16) float g_xz  [(size_t)NROWS * 2 * DINNER];
__device__ __align__(16) float g_xs  [(size_t)NROWS * DINNER];
__device__ __align__(16) float g_xdbl[(size_t)NROWS * XDBLW];
__device__ __align__(16) float g_dt  [(size_t)NROWS * DINNER];
__device__ __align__(16) float g_y   [(size_t)NROWS * DINNER];

// ---------------- int8 2-limb quantized operands (row-major, padded K) ----------------
__device__ __align__(16) char q_x1 [(size_t)NROWS * DMODEL];
__device__ __align__(16) char q_x2 [(size_t)NROWS * DMODEL];
__device__ __align__(16) char q_wi1[(size_t)(2*DINNER) * DMODEL];
__device__ __align__(16) char q_wi2[(size_t)(2*DINNER) * DMODEL];
__device__ __align__(16) char q_xs1[(size_t)NROWS * DINNER];
__device__ __align__(16) char q_xs2[(size_t)NROWS * DINNER];
__device__ __align__(16) char q_wx1[(size_t)128 * DINNER];
__device__ __align__(16) char q_wx2[(size_t)128 * DINNER];
__device__ __align__(16) char q_da1[(size_t)NROWS * 128];
__device__ __align__(16) char q_da2[(size_t)NROWS * 128];
__device__ __align__(16) char q_wd1[(size_t)DINNER * 128];
__device__ __align__(16) char q_wd2[(size_t)DINNER * 128];
__device__ __align__(16) char q_y1 [(size_t)NROWS * DINNER];
__device__ __align__(16) char q_y2 [(size_t)NROWS * DINNER];
__device__ __align__(16) char q_wo1[(size_t)DMODEL * DINNER];
__device__ __align__(16) char q_wo2[(size_t)DMODEL * DINNER];

__device__ __align__(16) float s_x [NROWS];
__device__ __align__(16) float s_wi[2 * DINNER];
__device__ __align__(16) float s_xs[NROWS];
__device__ __align__(16) float s_wx[128];
__device__ __align__(16) float s_da[NROWS];
__device__ __align__(16) float s_wd[DINNER];
__device__ __align__(16) float s_y [NROWS];
__device__ __align__(16) float s_wo[DMODEL];

// ---------------- helpers ----------------
__device__ __forceinline__ float softplus_f(float v) {
    return v > 20.f ? v : log1pf(expf(v));
}
__device__ __forceinline__ uint32_t smem_u32(const void* p) {
    uint32_t a;
    asm("{ .reg .u64 t; cvta.to.shared.u64 t, %1; cvt.u32.u64 %0, t; }" : "=r"(a) : "l"(p));
    return a;
}

#define CP_ASYNC16(dst, src) \
    asm volatile("cp.async.cg.shared.global [%0], [%1], 16;" \
        :: "r"(dst), "l"(src) : "memory")
#define CP_COMMIT()  asm volatile("cp.async.commit_group;" ::: "memory")
#define CP_WAIT0()   asm volatile("cp.async.wait_group 0;" ::: "memory")
#define CP_WAIT1()   asm volatile("cp.async.wait_group 1;" ::: "memory")

#define LDSM_X4(r0, r1, r2, r3, addr) \
    asm volatile("ldmatrix.sync.aligned.m8n8.x4.shared.b16 {%0,%1,%2,%3}, [%4];" \
        : "=r"(r0), "=r"(r1), "=r"(r2), "=r"(r3) : "r"(addr))

__device__ __forceinline__ void imma16832(int* c, const uint32_t* a, uint32_t b0, uint32_t b1) {
    asm volatile(
        "mma.sync.aligned.m16n8k32.row.col.s32.s8.s8.s32 "
        "{%0,%1,%2,%3}, {%4,%5,%6,%7}, {%8,%9}, {%0,%1,%2,%3};\n"
        : "+r"(c[0]), "+r"(c[1]), "+r"(c[2]), "+r"(c[3])
        : "r"(a[0]), "r"(a[1]), "r"(a[2]), "r"(a[3]), "r"(b0), "r"(b1));
}

// XOR swizzle for 128B rows, 16B granularity
__device__ __forceinline__ uint32_t sw_off(int row, int cb) {
    return (uint32_t)((row * 128 + cb) ^ ((row & 7) << 4));
}

// ============ per-row 2-limb int8 quantization ============
// a = s * (q1 + q2/128), s = rowAbsMax/127
__global__ __launch_bounds__(256) void quant_rows(
    const float* __restrict__ src, int ldsrc, int K, int Kpad, int validRows,
    char* __restrict__ q1, char* __restrict__ q2, float* __restrict__ scale)
{
    const int row = blockIdx.x;
    const int tid = threadIdx.x;
    __shared__ float warpmax[8];
    __shared__ float shInv;

    float mx = 0.f;
    if (row < validRows) {
        for (int k = tid; k < K; k += 256)
            mx = fmaxf(mx, fabsf(src[(size_t)row * ldsrc + k]));
    }
#pragma unroll
    for (int o = 16; o; o >>= 1) mx = fmaxf(mx, __shfl_xor_sync(~0u, mx, o));
    if ((tid & 31) == 0) warpmax[tid >> 5] = mx;
    __syncthreads();
    if (tid == 0) {
        float m = 0.f;
#pragma unroll
        for (int i = 0; i < 8; i++) m = fmaxf(m, warpmax[i]);
        if (m > 0.f) { shInv = 127.f / m; scale[row] = m / 127.f; }
        else         { shInv = 0.f;      scale[row] = 1.f; }
    }
    __syncthreads();
    const float inv = shInv;

    for (int k = tid * 8; k < Kpad; k += 2048) {
        char c1[8], c2[8];
#pragma unroll
        for (int e = 0; e < 8; e++) {
            const int kk = k + e;
            const float a = (row < validRows && kk < K) ? src[(size_t)row * ldsrc + kk] : 0.f;
            const float t  = a * inv;
            const float r1 = rintf(t);
            const float r2 = rintf((t - r1) * 128.f);
            c1[e] = (char)(int)r1;
            c2[e] = (char)(int)r2;
        }
        *(uint2*)(q1 + (size_t)row * Kpad + k) = *(const uint2*)c1;
        *(uint2*)(q2 + (size_t)row * Kpad + k) = *(const uint2*)c2;
    }
}

// ============ int8 2-limb GEMM: C = A(M,K)*W(N,K)^T via 3 IMMAs per k32 ============
// 128x128 CTA tile, BK=128, 3-stage cp.async pipeline, 256 threads (8 warps, warp=64x32).
// EPI: 0 none, 1 softplus(acc + bias[col])
template<int EPI>
__global__ __launch_bounds__(256, 1) void gemm_i8(
    const char* __restrict__ Aq1, const char* __restrict__ Aq2,
    const char* __restrict__ Wq1, const char* __restrict__ Wq2,
    const float* __restrict__ sA, const float* __restrict__ sB,
    float* __restrict__ C, int ldc, int N, int K, const float* __restrict__ bias)
{
    constexpr int TILE  = 128 * 128;   // bytes per operand tile (128 rows x 128B)
    constexpr int STAGE = 4 * TILE;    // 64 KB
    constexpr float INV128 = 1.f / 128.f;

    extern __shared__ char sm[];
    const uint32_t smBase = smem_u32(sm);

    const int tid  = threadIdx.x;
    const int lane = tid & 31;
    const int warp = tid >> 5;
    const int wr = warp >> 2;          // 0..1 (m)
    const int wc = warp & 3;           // 0..3 (n)
    const int mBase = blockIdx.y * 128;
    const int nBase = blockIdx.x * 128;

    const int ldRow = tid >> 3;        // 0..31
    const int ldC   = (tid & 7) * 16;  // byte chunk in 128B row
    const int nk = K >> 7;

    auto issue = [&](int c, int s) {
        const uint32_t st = smBase + s * STAGE;
        const int k0 = c << 7;
#pragma unroll
        for (int t = 0; t < 4; t++) {
            const int row = ldRow + t * 32;
            const uint32_t so = sw_off(row, ldC);
            const size_t aoff = (size_t)(mBase + row) * K + k0 + ldC;
            const size_t woff = (size_t)(nBase + row) * K + k0 + ldC;
            CP_ASYNC16(st + so,            Aq1 + aoff);
            CP_ASYNC16(st + TILE + so,     Aq2 + aoff);
            CP_ASYNC16(st + 2 * TILE + so, Wq1 + woff);
            CP_ASYNC16(st + 3 * TILE + so, Wq2 + woff);
        }
        CP_COMMIT();
    };

    int acc1[4][4][4], acc2[4][4][4];
#pragma unroll
    for (int i = 0; i < 4; i++)
#pragma unroll
        for (int j = 0; j < 4; j++)
#pragma unroll
            for (int e = 0; e < 4; e++) { acc1[i][j][e] = 0; acc2[i][j][e] = 0; }

    issue(0, 0);
    if (nk > 1) issue(1, 1);

    const int lr = lane & 15;
    const int lc = lane >> 4;

    for (int c = 0; c < nk; c++) {
        if (c + 1 < nk) { CP_WAIT1(); } else { CP_WAIT0(); }
        __syncthreads();
        if (c + 2 < nk) issue(c + 2, (c + 2) % 3);

        const uint32_t st  = smBase + (c % 3) * STAGE;
        const uint32_t a1t = st;
        const uint32_t a2t = st + TILE;
        const uint32_t w1t = st + 2 * TILE;
        const uint32_t w2t = st + 3 * TILE;

#pragma unroll
        for (int k32 = 0; k32 < 4; k32++) {
            const int cb = k32 * 32 + lc * 16;
            uint32_t B1[8], B2[8];
            const uint32_t o0 = sw_off(wc * 32 + lr, cb);
            const uint32_t o1 = sw_off(wc * 32 + 16 + lr, cb);
            LDSM_X4(B1[0], B1[1], B1[2], B1[3], w1t + o0);
            LDSM_X4(B1[4], B1[5], B1[6], B1[7], w1t + o1);
            LDSM_X4(B2[0], B2[1], B2[2], B2[3], w2t + o0);
            LDSM_X4(B2[4], B2[5], B2[6], B2[7], w2t + o1);
#pragma unroll
            for (int i = 0; i < 4; i++) {
                const uint32_t oA = sw_off(wr * 64 + i * 16 + lr, cb);
                uint32_t A1[4], A2[4];
                LDSM_X4(A1[0], A1[1], A1[2], A1[3], a1t + oA);
                LDSM_X4(A2[0], A2[1], A2[2], A2[3], a2t + oA);
#pragma unroll
                for (int j = 0; j < 4; j++) {
                    const int jj = j >> 1, sel = j & 1;
                    const uint32_t b10 = B1[jj * 4 + sel], b11 = B1[jj * 4 + sel + 2];
                    const uint32_t b20 = B2[jj * 4 + sel], b21 = B2[jj * 4 + sel + 2];
                    imma16832(acc1[i][j], A1, b10, b11);   // q1*q1
                    imma16832(acc2[i][j], A2, b10, b11);   // q2*q1
                    imma16832(acc2[i][j], A1, b20, b21);   // q1*q2
                }
            }
        }
    }

    // ---- epilogue: scale + (softplus) + store ----
#pragma unroll
    for (int i = 0; i < 4; i++) {
        const int row0 = mBase + wr * 64 + i * 16 + (lane >> 2);
        const float sa0 = sA[row0], sa1 = sA[row0 + 8];
#pragma unroll
        for (int j = 0; j < 4; j++) {
            const int col = nBase + wc * 32 + j * 8 + 2 * (lane & 3);
            if (col < N) {
                const float sb0 = sB[col], sb1 = sB[col + 1];
                float v00 = sa0 * sb0 * ((float)acc1[i][j][0] + (float)acc2[i][j][0] * INV128);
                float v01 = sa0 * sb1 * ((float)acc1[i][j][1] + (float)acc2[i][j][1] * INV128);
                float v10 = sa1 * sb0 * ((float)acc1[i][j][2] + (float)acc2[i][j][2] * INV128);
                float v11 = sa1 * sb1 * ((float)acc1[i][j][3] + (float)acc2[i][j][3] * INV128);
                if (EPI == 1) {
                    const float b0 = bias[col], b1 = bias[col + 1];
                    v00 = softplus_f(v00 + b0);
                    v01 = softplus_f(v01 + b1);
                    v10 = softplus_f(v10 + b0);
                    v11 = softplus_f(v11 + b1);
                }
                *(float2*)&C[(size_t)row0 * ldc + col] = make_float2(v00, v01);
                *(float2*)&C[(size_t)(row0 + 8) * ldc + col] = make_float2(v10, v11);
            }
        }
    }
}

// ---------------- causal depthwise conv (k=4) + bias + SiLU ----------------
#define CONV_LT 128
__global__ __launch_bounds__(256) void conv_silu_kernel(
    const float* __restrict__ cw, const float* __restrict__ cb)
{
    const int d  = blockIdx.x * 256 + threadIdx.x;
    const int b  = blockIdx.z;
    const int l0 = blockIdx.y * CONV_LT;

    const float w0 = cw[d * 4 + 0], w1 = cw[d * 4 + 1];
    const float w2 = cw[d * 4 + 2], w3 = cw[d * 4 + 3];
    const float bias = cb[d];

    const float* xp = g_xz + (size_t)b * LDIM * (2 * DINNER) + d;
    float xm3 = (l0 - 3 >= 0) ? xp[(size_t)(l0 - 3) * (2 * DINNER)] : 0.f;
    float xm2 = (l0 - 2 >= 0) ? xp[(size_t)(l0 - 2) * (2 * DINNER)] : 0.f;
    float xm1 = (l0 - 1 >= 0) ? xp[(size_t)(l0 - 1) * (2 * DINNER)] : 0.f;

    for (int l = l0; l < l0 + CONV_LT; l++) {
        const float xc = xp[(size_t)l * (2 * DINNER)];
        const float acc = bias + w0 * xm3 + w1 * xm2 + w2 * xm1 + w3 * xc;
        const float s = acc / (1.f + __expf(-acc));
        g_xs[((size_t)b * LDIM + l) * DINNER + d] = s;
        xm3 = xm2; xm2 = xm1; xm1 = xc;
    }
}

// ---------------- selective scan + D skip + SiLU(z) gate ----------------
__global__ __launch_bounds__(128) void scan_kernel(
    const float* __restrict__ A_log, const float* __restrict__ Dvec)
{
    const int b    = blockIdx.y;
    const int tid  = threadIdx.x;
    const int sub  = tid & 3;
    const int dloc = tid >> 2;
    const int d    = blockIdx.x * 32 + dloc;
    const int n0   = sub * 4;

    __shared__ float Bsh[32][DSTATE];
    __shared__ float Csh[32][DSTATE];

    float a[4], h[4];
#pragma unroll
    for (int n = 0; n < 4; n++) {
        a[n] = -__expf(A_log[d * DSTATE + n0 + n]);
        h[n] = 0.f;
    }
    const float Dd = Dvec[d];
    const size_t rowBase = (size_t)b * LDIM;

    for (int t0 = 0; t0 < LDIM; t0 += 32) {
        __syncthreads();
        for (int i = tid; i < 32 * 32; i += 128) {
            const int tl = i >> 5;
            const int c  = i & 31;
            const float v = g_xdbl[(rowBase + t0 + tl) * XDBLW + DTRANK + c];
            if (c < DSTATE) Bsh[tl][c] = v;
            else            Csh[tl][c - DSTATE] = v;
        }
        __syncthreads();

#pragma unroll 4
        for (int tl = 0; tl < 32; tl++) {
            const size_t r = rowBase + t0 + tl;
            const float dt = g_dt[r * DINNER + d];
            const float x  = g_xs[r * DINNER + d];
            const float z  = g_xz[r * (2 * DINNER) + DINNER + d];
            const float dtx = dt * x;
            float y = 0.f;
#pragma unroll
            for (int n = 0; n < 4; n++) {
                const float dA = __expf(dt * a[n]);
                h[n] = h[n] * dA + dtx * Bsh[tl][n0 + n];
                y += h[n] * Csh[tl][n0 + n];
            }
            y += __shfl_xor_sync(0xffffffffu, y, 1);
            y += __shfl_xor_sync(0xffffffffu, y, 2);
            y += Dd * x;
            const float sz = z / (1.f + __expf(-z));
            if (sub == 0) g_y[r * DINNER + d] = y * sz;
        }
    }
}

// ---------------- launch ----------------
extern "C" void kernel_launch(void* const* d_in, const int* in_sizes, int n_in,
                              void* d_out, int out_size)
{
    const float* x       = (const float*)d_in[0];
    const float* W_in    = (const float*)d_in[1];
    const float* conv_w  = (const float*)d_in[2];
    const float* conv_b  = (const float*)d_in[3];
    const float* W_xproj = (const float*)d_in[4];
    const float* W_dt    = (const float*)d_in[5];
    const float* b_dt    = (const float*)d_in[6];
    const float* A_log   = (const float*)d_in[7];
    const float* Dvec    = (const float*)d_in[8];
    const float* W_out   = (const float*)d_in[9];
    float* out = (float*)d_out;

    float *xz, *xs, *xdbl, *dtb, *y;
    cudaGetSymbolAddress((void**)&xz,   g_xz);
    cudaGetSymbolAddress((void**)&xs,   g_xs);
    cudaGetSymbolAddress((void**)&xdbl, g_xdbl);
    cudaGetSymbolAddress((void**)&dtb,  g_dt);
    cudaGetSymbolAddress((void**)&y,    g_y);

    char *x1, *x2, *wi1, *wi2, *xs1, *xs2, *wx1, *wx2;
    char *da1, *da2, *wd1, *wd2, *y1, *y2, *wo1, *wo2;
    float *sx, *swi, *sxs, *swx, *sda, *swd, *sy, *swo;
    cudaGetSymbolAddress((void**)&x1,  q_x1);  cudaGetSymbolAddress((void**)&x2,  q_x2);
    cudaGetSymbolAddress((void**)&wi1, q_wi1); cudaGetSymbolAddress((void**)&wi2, q_wi2);
    cudaGetSymbolAddress((void**)&xs1, q_xs1); cudaGetSymbolAddress((void**)&xs2, q_xs2);
    cudaGetSymbolAddress((void**)&wx1, q_wx1); cudaGetSymbolAddress((void**)&wx2, q_wx2);
    cudaGetSymbolAddress((void**)&da1, q_da1); cudaGetSymbolAddress((void**)&da2, q_da2);
    cudaGetSymbolAddress((void**)&wd1, q_wd1); cudaGetSymbolAddress((void**)&wd2, q_wd2);
    cudaGetSymbolAddress((void**)&y1,  q_y1);  cudaGetSymbolAddress((void**)&y2,  q_y2);
    cudaGetSymbolAddress((void**)&wo1, q_wo1); cudaGetSymbolAddress((void**)&wo2, q_wo2);
    cudaGetSymbolAddress((void**)&sx,  s_x);   cudaGetSymbolAddress((void**)&swi, s_wi);
    cudaGetSymbolAddress((void**)&sxs, s_xs);  cudaGetSymbolAddress((void**)&swx, s_wx);
    cudaGetSymbolAddress((void**)&sda, s_da);  cudaGetSymbolAddress((void**)&swd, s_wd);
    cudaGetSymbolAddress((void**)&sy,  s_y);   cudaGetSymbolAddress((void**)&swo, s_wo);

    constexpr int SMEM = 3 * 4 * 128 * 128;  // 196608 B
    cudaFuncSetAttribute((const void*)gemm_i8<0>,
                         cudaFuncAttributeMaxDynamicSharedMemorySize, SMEM);
    cudaFuncSetAttribute((const void*)gemm_i8<1>,
                         cudaFuncAttributeMaxDynamicSharedMemorySize, SMEM);

    // ---- quantize inputs for in_proj ----
    quant_rows<<<NROWS, 256>>>(x,    DMODEL, DMODEL, DMODEL, NROWS,      x1,  x2,  sx);
    quant_rows<<<2 * DINNER, 256>>>(W_in, DMODEL, DMODEL, DMODEL, 2 * DINNER, wi1, wi2, swi);

    // 1. in_proj: xz = x @ W_in^T  (M=4096, N=4096, K=1024)
    gemm_i8<0><<<dim3(2 * DINNER / 128, NROWS / 128), 256, SMEM>>>(
        x1, x2, wi1, wi2, sx, swi, xz, 2 * DINNER, 2 * DINNER, DMODEL, nullptr);

    // 2. conv + SiLU
    conv_silu_kernel<<<dim3(DINNER / 256, LDIM / CONV_LT, BDIM), 256>>>(conv_w, conv_b);

    // ---- quantize for x_proj ----
    quant_rows<<<NROWS, 256>>>(xs,      DINNER, DINNER, DINNER, NROWS, xs1, xs2, sxs);
    quant_rows<<<128, 256>>>(W_xproj, DINNER, DINNER, DINNER, XDBLW, wx1, wx2, swx);

    // 3. x_proj: x_dbl = xs @ W_xproj^T  (M=4096, N=96, K=2048)
    gemm_i8<0><<<dim3(1, NROWS / 128), 256, SMEM>>>(
        xs1, xs2, wx1, wx2, sxs, swx, xdbl, XDBLW, XDBLW, DINNER, nullptr);

    // ---- quantize for dt gemm (K=64 padded to 128) ----
    quant_rows<<<NROWS, 256>>>(xdbl, XDBLW,  DTRANK, 128, NROWS,  da1, da2, sda);
    quant_rows<<<DINNER, 256>>>(W_dt, DTRANK, DTRANK, 128, DINNER, wd1, wd2, swd);

    // 4. dt = softplus(x_dbl[:, :64] @ W_dt^T + b_dt)  (M=4096, N=2048, K=128pad)
    gemm_i8<1><<<dim3(DINNER / 128, NROWS / 128), 256, SMEM>>>(
        da1, da2, wd1, wd2, sda, swd, dtb, DINNER, DINNER, 128, b_dt);

    // 5. selective scan + D skip + gate
    scan_kernel<<<dim3(DINNER / 32, BDIM), 128>>>(A_log, Dvec);

    // ---- quantize for out_proj ----
    quant_rows<<<NROWS, 256>>>(y,     DINNER, DINNER, DINNER, NROWS,  y1,  y2,  sy);
    quant_rows<<<DMODEL, 256>>>(W_out, DINNER, DINNER, DINNER, DMODEL, wo1, wo2, swo);

    // 6. out_proj: out = y @ W_out^T  (M=4096, N=1024, K=2048)
    gemm_i8<0><<<dim3(DMODEL / 128, NROWS / 128), 256, SMEM>>>(
        y1, y2, wo1, wo2, sy, swo, out, DMODEL, DMODEL, DINNER, nullptr);
}

// round 7
// speedup vs baseline: 1.3336x; 1.3336x over previous
#include <cuda_runtime.h>
#include <cuda_bf16.h>
#include <math.h>
#include <stdint.h>

#define BDIM   2
#define LDIM   2048
#define DMODEL 1024
#define DINNER 2048
#define DSTATE 16
#define DTRANK 64
#define DCONV  4
#define NROWS  (BDIM * LDIM)          // 4096
#define XDBLW  (DTRANK + 2 * DSTATE)  // 96

// ---------------- f32 scratch ----------------
__device__ __align__(16) float g_xz  [(size_t)NROWS * 2 * DINNER];
__device__ __align__(16) float g_xs  [(size_t)NROWS * DINNER];
__device__ __align__(16) float g_xdbl[(size_t)NROWS * XDBLW];
__device__ __align__(16) float g_dt  [(size_t)NROWS * DINNER];

// ---------------- packed bf16 hi/lo (plain row-major [rows][K]) ----------------
__device__ __align__(16) __nv_bfloat16 g_xh [(size_t)NROWS * DMODEL];
__device__ __align__(16) __nv_bfloat16 g_xl [(size_t)NROWS * DMODEL];
__device__ __align__(16) __nv_bfloat16 g_wih[(size_t)(2*DINNER) * DMODEL];
__device__ __align__(16) __nv_bfloat16 g_wil[(size_t)(2*DINNER) * DMODEL];
__device__ __align__(16) __nv_bfloat16 g_xsh[(size_t)NROWS * DINNER];
__device__ __align__(16) __nv_bfloat16 g_xsl[(size_t)NROWS * DINNER];
__device__ __align__(16) __nv_bfloat16 g_wxh[(size_t)XDBLW * DINNER];
__device__ __align__(16) __nv_bfloat16 g_wxl[(size_t)XDBLW * DINNER];
__device__ __align__(16) __nv_bfloat16 g_dah[(size_t)NROWS * DTRANK];
__device__ __align__(16) __nv_bfloat16 g_dal[(size_t)NROWS * DTRANK];
__device__ __align__(16) __nv_bfloat16 g_wdh[(size_t)DINNER * DTRANK];
__device__ __align__(16) __nv_bfloat16 g_wdl[(size_t)DINNER * DTRANK];
__device__ __align__(16) __nv_bfloat16 g_yh [(size_t)NROWS * DINNER];
__device__ __align__(16) __nv_bfloat16 g_yl [(size_t)NROWS * DINNER];
__device__ __align__(16) __nv_bfloat16 g_woh[(size_t)DMODEL * DINNER];
__device__ __align__(16) __nv_bfloat16 g_wol[(size_t)DMODEL * DINNER];

// ---------------- helpers ----------------
__device__ __forceinline__ float softplus_f(float v) {
    return v > 20.f ? v : log1pf(expf(v));
}
__device__ __forceinline__ uint32_t smem_u32(const void* p) {
    uint32_t a;
    asm("{ .reg .u64 t; cvta.to.shared.u64 t, %1; cvt.u32.u64 %0, t; }" : "=r"(a) : "l"(p));
    return a;
}

#define CP_ASYNC16(dst, src, srcsize) \
    asm volatile("cp.async.cg.shared.global [%0], [%1], 16, %2;" \
        :: "r"(dst), "l"(src), "r"(srcsize) : "memory")
#define CP_COMMIT()  asm volatile("cp.async.commit_group;" ::: "memory")
#define CP_WAIT0()   asm volatile("cp.async.wait_group 0;" ::: "memory")
#define CP_WAIT1()   asm volatile("cp.async.wait_group 1;" ::: "memory")

#define LDSM_X4(r0, r1, r2, r3, addr) \
    asm volatile("ldmatrix.sync.aligned.m8n8.x4.shared.b16 {%0,%1,%2,%3}, [%4];" \
        : "=r"(r0), "=r"(r1), "=r"(r2), "=r"(r3) : "r"(addr))

__device__ __forceinline__ void mma16816(float* c, const uint32_t* a, uint32_t b0, uint32_t b1) {
    asm volatile(
        "mma.sync.aligned.m16n8k16.row.col.f32.bf16.bf16.f32 "
        "{%0,%1,%2,%3}, {%4,%5,%6,%7}, {%8,%9}, {%0,%1,%2,%3};\n"
        : "+f"(c[0]), "+f"(c[1]), "+f"(c[2]), "+f"(c[3])
        : "r"(a[0]), "r"(a[1]), "r"(a[2]), "r"(a[3]), "r"(b0), "r"(b1));
}

// XOR swizzle for 128B rows, 16B granularity
__device__ __forceinline__ uint32_t sw_off(int row, int cb) {
    return (uint32_t)((row * 128 + cb) ^ ((row & 7) << 4));
}

// ============ pack fp32 -> plain row-major bf16 hi/lo ============
__global__ __launch_bounds__(256) void pack_plain(
    const float* __restrict__ src, int ldsrc, int K,
    __nv_bfloat16* __restrict__ hi, __nv_bfloat16* __restrict__ lo, int total8)
{
    const int idx = blockIdx.x * 256 + threadIdx.x;
    if (idx >= total8) return;
    const int kd = K >> 3;
    const int m  = idx / kd;
    const int k  = (idx - m * kd) << 3;
    const float4 a = *(const float4*)&src[(size_t)m * ldsrc + k];
    const float4 b = *(const float4*)&src[(size_t)m * ldsrc + k + 4];
    const float v[8] = {a.x, a.y, a.z, a.w, b.x, b.y, b.z, b.w};
    __nv_bfloat16 h[8], l[8];
#pragma unroll
    for (int e = 0; e < 8; e++) {
        h[e] = __float2bfloat16(v[e]);
        l[e] = __float2bfloat16(v[e] - __bfloat162float(h[e]));
    }
    *(uint4*)(hi + (size_t)m * K + k) = *(const uint4*)h;
    *(uint4*)(lo + (size_t)m * K + k) = *(const uint4*)l;
}

// ============ GEMM: C = A(M,K) * W(N,K)^T, bf16 split-2 (3 MMAs) ============
// 128x64 CTA tile, BK=64, double-buffered, 256 threads (8 warps: 4m x 2n, warp=32x32),
// 2 CTAs/SM. EPI: 0 none, 1 softplus(acc + bias[col])
template<int EPI>
__global__ __launch_bounds__(256, 2) void gemm_mma2(
    const __nv_bfloat16* __restrict__ Ah, const __nv_bfloat16* __restrict__ Al,
    const __nv_bfloat16* __restrict__ Wh, const __nv_bfloat16* __restrict__ Wl,
    float* __restrict__ C, int ldc, int N, int K, const float* __restrict__ bias)
{
    constexpr int TILE_A = 128 * 128;      // bytes (128 rows x 64 bf16)
    constexpr int TILE_W = 64 * 128;       // bytes (64 rows x 64 bf16)
    constexpr int STAGE  = 2 * TILE_A + 2 * TILE_W;  // 49152 B

    extern __shared__ char sm[];
    const uint32_t smBase = smem_u32(sm);

    const int tid  = threadIdx.x;
    const int lane = tid & 31;
    const int warp = tid >> 5;
    const int wr = warp >> 1;              // 0..3 (m)
    const int wc = warp & 1;               // 0..1 (n)
    const int mBase = blockIdx.y * 128;
    const int nBase = blockIdx.x * 64;

    const int ldRow = tid >> 3;            // 0..31
    const int ldC   = tid & 7;             // 16B chunk 0..7
    const int nk = K >> 6;

    auto issue = [&](int c, int s) {
        const int k0 = c << 6;
        const uint32_t st = smBase + s * STAGE;
#pragma unroll
        for (int t = 0; t < 4; t++) {
            const int row = ldRow + t * 32;
            const uint32_t so = sw_off(row, ldC * 16);
            const size_t aoff = (size_t)(mBase + row) * K + k0 + ldC * 8;
            CP_ASYNC16(st + so,          Ah + aoff, 16);
            CP_ASYNC16(st + TILE_A + so, Al + aoff, 16);
        }
#pragma unroll
        for (int t = 0; t < 2; t++) {
            const int row = ldRow + t * 32;
            const uint32_t so = sw_off(row, ldC * 16);
            const int wrow = nBase + row;
            const int ok = (wrow < N) ? 16 : 0;
            const size_t woff = (size_t)(ok ? wrow : 0) * K + ldC * 8 + k0;
            CP_ASYNC16(st + 2 * TILE_A + so,          Wh + woff, ok);
            CP_ASYNC16(st + 2 * TILE_A + TILE_W + so, Wl + woff, ok);
        }
        CP_COMMIT();
    };

    float acc[2][4][4];
#pragma unroll
    for (int i = 0; i < 2; i++)
#pragma unroll
        for (int j = 0; j < 4; j++)
#pragma unroll
            for (int e = 0; e < 4; e++) acc[i][j][e] = 0.f;

    issue(0, 0);
    if (nk > 1) issue(1, 1);

    const int lr = lane & 15;
    const int lc = lane >> 4;

    for (int c = 0; c < nk; c++) {
        if (c == nk - 1) { CP_WAIT0(); } else { CP_WAIT1(); }
        __syncthreads();

        const uint32_t st  = smBase + (c & 1) * STAGE;
        const uint32_t aHi = st;
        const uint32_t aLo = st + TILE_A;
        const uint32_t wHi = st + 2 * TILE_A;
        const uint32_t wLo = st + 2 * TILE_A + TILE_W;

#pragma unroll
        for (int k16 = 0; k16 < 4; k16++) {
            const int cb = k16 * 32 + lc * 16;
            uint32_t bh[8], bl[8];
            {
                const uint32_t o0 = sw_off(wc * 32 + lr, cb);
                const uint32_t o1 = sw_off(wc * 32 + 16 + lr, cb);
                LDSM_X4(bh[0], bh[1], bh[2], bh[3], wHi + o0);
                LDSM_X4(bh[4], bh[5], bh[6], bh[7], wHi + o1);
                LDSM_X4(bl[0], bl[1], bl[2], bl[3], wLo + o0);
                LDSM_X4(bl[4], bl[5], bl[6], bl[7], wLo + o1);
            }
#pragma unroll
            for (int i = 0; i < 2; i++) {
                const uint32_t oA = sw_off(wr * 32 + i * 16 + lr, cb);
                uint32_t ah[4], al[4];
                LDSM_X4(ah[0], ah[1], ah[2], ah[3], aHi + oA);
                LDSM_X4(al[0], al[1], al[2], al[3], aLo + oA);
#pragma unroll
                for (int j = 0; j < 4; j++) {
                    const int jj = j >> 1, sel = j & 1;
                    const uint32_t b0h = bh[jj * 4 + sel], b1h = bh[jj * 4 + sel + 2];
                    const uint32_t b0l = bl[jj * 4 + sel], b1l = bl[jj * 4 + sel + 2];
                    mma16816(acc[i][j], ah, b0h, b1h);   // hi*hi
                    mma16816(acc[i][j], al, b0h, b1h);   // lo*hi
                    mma16816(acc[i][j], ah, b0l, b1l);   // hi*lo
                }
            }
        }

        if (c + 2 < nk) {
            __syncthreads();
            issue(c + 2, c & 1);
        }
    }

    // ---- epilogue: direct register stores ----
#pragma unroll
    for (int i = 0; i < 2; i++) {
        const int m0 = mBase + wr * 32 + i * 16 + (lane >> 2);
#pragma unroll
        for (int j = 0; j < 4; j++) {
            const int col = nBase + wc * 32 + j * 8 + 2 * (lane & 3);
            if (col < N) {
                float2 v0 = make_float2(acc[i][j][0], acc[i][j][1]);
                float2 v1 = make_float2(acc[i][j][2], acc[i][j][3]);
                if (EPI == 1) {
                    const float b0 = bias[col], b1 = bias[col + 1];
                    v0.x = softplus_f(v0.x + b0);
                    v0.y = softplus_f(v0.y + b1);
                    v1.x = softplus_f(v1.x + b0);
                    v1.y = softplus_f(v1.y + b1);
                }
                *(float2*)&C[(size_t)m0 * ldc + col] = v0;
                *(float2*)&C[(size_t)(m0 + 8) * ldc + col] = v1;
            }
        }
    }
}

// ---------------- causal depthwise conv (k=4) + bias + SiLU, fused bf16 split ----------------
#define CONV_LT 32
__global__ __launch_bounds__(256) void conv_silu_kernel(
    const float* __restrict__ cw, const float* __restrict__ cb)
{
    const int d  = blockIdx.x * 256 + threadIdx.x;
    const int b  = blockIdx.z;
    const int l0 = blockIdx.y * CONV_LT;

    const float w0 = cw[d * 4 + 0], w1 = cw[d * 4 + 1];
    const float w2 = cw[d * 4 + 2], w3 = cw[d * 4 + 3];
    const float bias = cb[d];

    const float* xp = g_xz + (size_t)b * LDIM * (2 * DINNER) + d;
    float xm3 = (l0 - 3 >= 0) ? xp[(size_t)(l0 - 3) * (2 * DINNER)] : 0.f;
    float xm2 = (l0 - 2 >= 0) ? xp[(size_t)(l0 - 2) * (2 * DINNER)] : 0.f;
    float xm1 = (l0 - 1 >= 0) ? xp[(size_t)(l0 - 1) * (2 * DINNER)] : 0.f;

    for (int l = l0; l < l0 + CONV_LT; l++) {
        const float xc = xp[(size_t)l * (2 * DINNER)];
        const float acc = bias + w0 * xm3 + w1 * xm2 + w2 * xm1 + w3 * xc;
        const float s = acc / (1.f + __expf(-acc));
        const size_t o = ((size_t)b * LDIM + l) * DINNER + d;
        g_xs[o] = s;
        const __nv_bfloat16 h = __float2bfloat16(s);
        g_xsh[o] = h;
        g_xsl[o] = __float2bfloat16(s - __bfloat162float(h));
        xm3 = xm2; xm2 = xm1; xm1 = xc;
    }
}

// ---------------- selective scan + D skip + SiLU(z) gate, fused bf16 split out ----------------
__global__ __launch_bounds__(128) void scan_kernel(
    const float* __restrict__ A_log, const float* __restrict__ Dvec)
{
    const int b    = blockIdx.y;
    const int tid  = threadIdx.x;
    const int sub  = tid & 3;
    const int dloc = tid >> 2;
    const int d    = blockIdx.x * 32 + dloc;
    const int n0   = sub * 4;

    __shared__ float Bsh[32][DSTATE];
    __shared__ float Csh[32][DSTATE];

    float a[4], h[4];
#pragma unroll
    for (int n = 0; n < 4; n++) {
        a[n] = -__expf(A_log[d * DSTATE + n0 + n]);
        h[n] = 0.f;
    }
    const float Dd = Dvec[d];
    const size_t rowBase = (size_t)b * LDIM;

    for (int t0 = 0; t0 < LDIM; t0 += 32) {
        __syncthreads();
        for (int i = tid; i < 32 * 32; i += 128) {
            const int tl = i >> 5;
            const int c  = i & 31;
            const float v = g_xdbl[(rowBase + t0 + tl) * XDBLW + DTRANK + c];
            if (c < DSTATE) Bsh[tl][c] = v;
            else            Csh[tl][c - DSTATE] = v;
        }
        __syncthreads();

#pragma unroll 4
        for (int tl = 0; tl < 32; tl++) {
            const size_t r = rowBase + t0 + tl;
            const float dt = g_dt[r * DINNER + d];
            const float x  = g_xs[r * DINNER + d];
            const float z  = g_xz[r * (2 * DINNER) + DINNER + d];
            const float dtx = dt * x;
            float y = 0.f;
#pragma unroll
            for (int n = 0; n < 4; n++) {
                const float dA = __expf(dt * a[n]);
                h[n] = h[n] * dA + dtx * Bsh[tl][n0 + n];
                y += h[n] * Csh[tl][n0 + n];
            }
            y += __shfl_xor_sync(0xffffffffu, y, 1);
            y += __shfl_xor_sync(0xffffffffu, y, 2);
            y += Dd * x;
            const float sz = z / (1.f + __expf(-z));
            if (sub == 0) {
                const float yv = y * sz;
                const __nv_bfloat16 hh = __float2bfloat16(yv);
                g_yh[r * DINNER + d] = hh;
                g_yl[r * DINNER + d] = __float2bfloat16(yv - __bfloat162float(hh));
            }
        }
    }
}

// ---------------- launch ----------------
extern "C" void kernel_launch(void* const* d_in, const int* in_sizes, int n_in,
                              void* d_out, int out_size)
{
    const float* x       = (const float*)d_in[0];
    const float* W_in    = (const float*)d_in[1];
    const float* conv_w  = (const float*)d_in[2];
    const float* conv_b  = (const float*)d_in[3];
    const float* W_xproj = (const float*)d_in[4];
    const float* W_dt    = (const float*)d_in[5];
    const float* b_dt    = (const float*)d_in[6];
    const float* A_log   = (const float*)d_in[7];
    const float* Dvec    = (const float*)d_in[8];
    const float* W_out   = (const float*)d_in[9];
    float* out = (float*)d_out;

    float *xz, *xdbl, *dtb;
    cudaGetSymbolAddress((void**)&xz,   g_xz);
    cudaGetSymbolAddress((void**)&xdbl, g_xdbl);
    cudaGetSymbolAddress((void**)&dtb,  g_dt);

    __nv_bfloat16 *xh, *xl, *wih, *wil, *xsh, *xsl, *wxh, *wxl;
    __nv_bfloat16 *dah, *dal, *wdh, *wdl, *yh, *yl, *woh, *wol;
    cudaGetSymbolAddress((void**)&xh,  g_xh);  cudaGetSymbolAddress((void**)&xl,  g_xl);
    cudaGetSymbolAddress((void**)&wih, g_wih); cudaGetSymbolAddress((void**)&wil, g_wil);
    cudaGetSymbolAddress((void**)&xsh, g_xsh); cudaGetSymbolAddress((void**)&xsl, g_xsl);
    cudaGetSymbolAddress((void**)&wxh, g_wxh); cudaGetSymbolAddress((void**)&wxl, g_wxl);
    cudaGetSymbolAddress((void**)&dah, g_dah); cudaGetSymbolAddress((void**)&dal, g_dal);
    cudaGetSymbolAddress((void**)&wdh, g_wdh); cudaGetSymbolAddress((void**)&wdl, g_wdl);
    cudaGetSymbolAddress((void**)&yh,  g_yh);  cudaGetSymbolAddress((void**)&yl,  g_yl);
    cudaGetSymbolAddress((void**)&woh, g_woh); cudaGetSymbolAddress((void**)&wol, g_wol);

    constexpr int SMEM = 2 * (2 * 128 * 128 + 2 * 64 * 128);  // 98304 B
    cudaFuncSetAttribute((const void*)gemm_mma2<0>,
                         cudaFuncAttributeMaxDynamicSharedMemorySize, SMEM);
    cudaFuncSetAttribute((const void*)gemm_mma2<1>,
                         cudaFuncAttributeMaxDynamicSharedMemorySize, SMEM);

    // ---- packs for in_proj ----
    {
        int t8 = NROWS * DMODEL / 8;
        pack_plain<<<(t8 + 255) / 256, 256>>>(x, DMODEL, DMODEL, xh, xl, t8);
        t8 = 2 * DINNER * DMODEL / 8;
        pack_plain<<<(t8 + 255) / 256, 256>>>(W_in, DMODEL, DMODEL, wih, wil, t8);
    }

    // 1. in_proj: xz = x @ W_in^T  (M=4096, N=4096, K=1024)
    gemm_mma2<0><<<dim3(4096 / 64, 32), 256, SMEM>>>(
        xh, xl, wih, wil, xz, 2 * DINNER, 2 * DINNER, DMODEL, nullptr);

    // 2. conv + SiLU (+ bf16 split of xs)
    conv_silu_kernel<<<dim3(DINNER / 256, LDIM / CONV_LT, BDIM), 256>>>(conv_w, conv_b);

    // ---- pack W_xproj ----
    {
        int t8 = XDBLW * DINNER / 8;
        pack_plain<<<(t8 + 255) / 256, 256>>>(W_xproj, DINNER, DINNER, wxh, wxl, t8);
    }

    // 3. x_proj: x_dbl = xs @ W_xproj^T  (M=4096, N=96, K=2048)
    gemm_mma2<0><<<dim3(2, 32), 256, SMEM>>>(
        xsh, xsl, wxh, wxl, xdbl, XDBLW, XDBLW, DINNER, nullptr);

    // ---- packs for dt gemm ----
    {
        int t8 = NROWS * DTRANK / 8;
        pack_plain<<<(t8 + 255) / 256, 256>>>(xdbl, XDBLW, DTRANK, dah, dal, t8);
        t8 = DINNER * DTRANK / 8;
        pack_plain<<<(t8 + 255) / 256, 256>>>(W_dt, DTRANK, DTRANK, wdh, wdl, t8);
    }

    // 4. dt = softplus(x_dbl[:, :64] @ W_dt^T + b_dt)  (M=4096, N=2048, K=64)
    gemm_mma2<1><<<dim3(DINNER / 64, 32), 256, SMEM>>>(
        dah, dal, wdh, wdl, dtb, DINNER, DINNER, DTRANK, b_dt);

    // 5. selective scan + D skip + gate (+ bf16 split of y)
    scan_kernel<<<dim3(DINNER / 32, BDIM), 128>>>(A_log, Dvec);

    // ---- pack W_out ----
    {
        int t8 = DMODEL * DINNER / 8;
        pack_plain<<<(t8 + 255) / 256, 256>>>(W_out, DINNER, DINNER, woh, wol, t8);
    }

    // 6. out_proj: out = y @ W_out^T  (M=4096, N=1024, K=2048)
    gemm_mma2<0><<<dim3(DMODEL / 64, 32), 256, SMEM>>>(
        yh, yl, woh, wol, out, DMODEL, DMODEL, DINNER, nullptr);
}

// round 8
// speedup vs baseline: 1.3379x; 1.0032x over previous
#include <cuda_runtime.h>
#include <cuda_fp16.h>
#include <math.h>
#include <stdint.h>

#define BDIM   2
#define LDIM   2048
#define DMODEL 1024
#define DINNER 2048
#define DSTATE 16
#define DTRANK 64
#define DCONV  4
#define NROWS  (BDIM * LDIM)          // 4096
#define XDBLW  (DTRANK + 2 * DSTATE)  // 96

#define LO_SCALE   2048.0f
#define LO_INV     (1.0f / 2048.0f)

// ---------------- f32 scratch ----------------
__device__ __align__(16) float g_xz  [(size_t)NROWS * 2 * DINNER];
__device__ __align__(16) float g_xs  [(size_t)NROWS * DINNER];
__device__ __align__(16) float g_xdbl[(size_t)NROWS * XDBLW];
__device__ __align__(16) float g_dt  [(size_t)NROWS * DINNER];

// ---------------- packed fp16 hi/lo (plain row-major [rows][K]) ----------------
__device__ __align__(16) __half g_xh [(size_t)NROWS * DMODEL];
__device__ __align__(16) __half g_xl [(size_t)NROWS * DMODEL];
__device__ __align__(16) __half g_wih[(size_t)(2*DINNER) * DMODEL];
__device__ __align__(16) __half g_wil[(size_t)(2*DINNER) * DMODEL];
__device__ __align__(16) __half g_xsh[(size_t)NROWS * DINNER];
__device__ __align__(16) __half g_xsl[(size_t)NROWS * DINNER];
__device__ __align__(16) __half g_wxh[(size_t)XDBLW * DINNER];
__device__ __align__(16) __half g_wxl[(size_t)XDBLW * DINNER];
__device__ __align__(16) __half g_dah[(size_t)NROWS * DTRANK];
__device__ __align__(16) __half g_dal[(size_t)NROWS * DTRANK];
__device__ __align__(16) __half g_wdh[(size_t)DINNER * DTRANK];
__device__ __align__(16) __half g_wdl[(size_t)DINNER * DTRANK];
__device__ __align__(16) __half g_yh [(size_t)NROWS * DINNER];
__device__ __align__(16) __half g_yl [(size_t)NROWS * DINNER];
__device__ __align__(16) __half g_woh[(size_t)DMODEL * DINNER];
__device__ __align__(16) __half g_wol[(size_t)DMODEL * DINNER];

// ---------------- helpers ----------------
__device__ __forceinline__ float softplus_f(float v) {
    return v > 20.f ? v : log1pf(expf(v));
}
__device__ __forceinline__ uint32_t smem_u32(const void* p) {
    uint32_t a;
    asm("{ .reg .u64 t; cvta.to.shared.u64 t, %1; cvt.u32.u64 %0, t; }" : "=r"(a) : "l"(p));
    return a;
}

#define CP_ASYNC16(dst, src, srcsize) \
    asm volatile("cp.async.cg.shared.global [%0], [%1], 16, %2;" \
        :: "r"(dst), "l"(src), "r"(srcsize) : "memory")
#define CP_COMMIT()  asm volatile("cp.async.commit_group;" ::: "memory")
#define CP_WAIT0()   asm volatile("cp.async.wait_group 0;" ::: "memory")
#define CP_WAIT1()   asm volatile("cp.async.wait_group 1;" ::: "memory")

#define LDSM_X4(r0, r1, r2, r3, addr) \
    asm volatile("ldmatrix.sync.aligned.m8n8.x4.shared.b16 {%0,%1,%2,%3}, [%4];" \
        : "=r"(r0), "=r"(r1), "=r"(r2), "=r"(r3) : "r"(addr))

// fp16 inputs, fp32 accumulate (main term)
__device__ __forceinline__ void mma_f32(float* c, const uint32_t* a, uint32_t b0, uint32_t b1) {
    asm volatile(
        "mma.sync.aligned.m16n8k16.row.col.f32.f16.f16.f32 "
        "{%0,%1,%2,%3}, {%4,%5,%6,%7}, {%8,%9}, {%0,%1,%2,%3};\n"
        : "+f"(c[0]), "+f"(c[1]), "+f"(c[2]), "+f"(c[3])
        : "r"(a[0]), "r"(a[1]), "r"(a[2]), "r"(a[3]), "r"(b0), "r"(b1));
}
// fp16 inputs, fp16 accumulate (correction terms — 2x rate on GeForce-style HMMA)
__device__ __forceinline__ void mma_f16(uint32_t* c, const uint32_t* a, uint32_t b0, uint32_t b1) {
    asm volatile(
        "mma.sync.aligned.m16n8k16.row.col.f16.f16.f16.f16 "
        "{%0,%1}, {%2,%3,%4,%5}, {%6,%7}, {%0,%1};\n"
        : "+r"(c[0]), "+r"(c[1])
        : "r"(a[0]), "r"(a[1]), "r"(a[2]), "r"(a[3]), "r"(b0), "r"(b1));
}

// XOR swizzle for 128B rows, 16B granularity
__device__ __forceinline__ uint32_t sw_off(int row, int cb) {
    return (uint32_t)((row * 128 + cb) ^ ((row & 7) << 4));
}

__device__ __forceinline__ void split_h(float v, __half& h, __half& l) {
    h = __float2half_rn(v);
    l = __float2half_rn((v - __half2float(h)) * LO_SCALE);
}

// ============ pack fp32 -> plain row-major fp16 hi/lo (lo scaled x2048) ============
__global__ __launch_bounds__(256) void pack_plain(
    const float* __restrict__ src, int ldsrc, int K,
    __half* __restrict__ hi, __half* __restrict__ lo, int total8)
{
    const int idx = blockIdx.x * 256 + threadIdx.x;
    if (idx >= total8) return;
    const int kd = K >> 3;
    const int m  = idx / kd;
    const int k  = (idx - m * kd) << 3;
    const float4 a = *(const float4*)&src[(size_t)m * ldsrc + k];
    const float4 b = *(const float4*)&src[(size_t)m * ldsrc + k + 4];
    const float v[8] = {a.x, a.y, a.z, a.w, b.x, b.y, b.z, b.w};
    __half h[8], l[8];
#pragma unroll
    for (int e = 0; e < 8; e++) split_h(v[e], h[e], l[e]);
    *(uint4*)(hi + (size_t)m * K + k) = *(const uint4*)h;
    *(uint4*)(lo + (size_t)m * K + k) = *(const uint4*)l;
}

// ============ GEMM: C = A(M,K) * W(N,K)^T, fp16 split-2 ============
// main term f32-accum MMA, corrections f16-accum MMAs.
// 128x64 CTA tile, BK=64, double-buffered, 256 threads (8 warps: 4m x 2n), 2 CTAs/SM.
// EPI: 0 none, 1 softplus(acc + bias[col])
template<int EPI>
__global__ __launch_bounds__(256, 2) void gemm_mma2(
    const __half* __restrict__ Ah, const __half* __restrict__ Al,
    const __half* __restrict__ Wh, const __half* __restrict__ Wl,
    float* __restrict__ C, int ldc, int N, int K, const float* __restrict__ bias)
{
    constexpr int TILE_A = 128 * 128;      // bytes (128 rows x 64 fp16)
    constexpr int TILE_W = 64 * 128;       // bytes (64 rows x 64 fp16)
    constexpr int STAGE  = 2 * TILE_A + 2 * TILE_W;  // 49152 B

    extern __shared__ char sm[];
    const uint32_t smBase = smem_u32(sm);

    const int tid  = threadIdx.x;
    const int lane = tid & 31;
    const int warp = tid >> 5;
    const int wr = warp >> 1;              // 0..3 (m)
    const int wc = warp & 1;               // 0..1 (n)
    const int mBase = blockIdx.y * 128;
    const int nBase = blockIdx.x * 64;

    const int ldRow = tid >> 3;            // 0..31
    const int ldC   = tid & 7;             // 16B chunk 0..7
    const int nk = K >> 6;

    auto issue = [&](int c, int s) {
        const int k0 = c << 6;
        const uint32_t st = smBase + s * STAGE;
#pragma unroll
        for (int t = 0; t < 4; t++) {
            const int row = ldRow + t * 32;
            const uint32_t so = sw_off(row, ldC * 16);
            const size_t aoff = (size_t)(mBase + row) * K + k0 + ldC * 8;
            CP_ASYNC16(st + so,          Ah + aoff, 16);
            CP_ASYNC16(st + TILE_A + so, Al + aoff, 16);
        }
#pragma unroll
        for (int t = 0; t < 2; t++) {
            const int row = ldRow + t * 32;
            const uint32_t so = sw_off(row, ldC * 16);
            const int wrow = nBase + row;
            const int ok = (wrow < N) ? 16 : 0;
            const size_t woff = (size_t)(ok ? wrow : 0) * K + ldC * 8 + k0;
            CP_ASYNC16(st + 2 * TILE_A + so,          Wh + woff, ok);
            CP_ASYNC16(st + 2 * TILE_A + TILE_W + so, Wl + woff, ok);
        }
        CP_COMMIT();
    };

    float    acc [2][4][4];
    uint32_t accc[2][4][2];
#pragma unroll
    for (int i = 0; i < 2; i++)
#pragma unroll
        for (int j = 0; j < 4; j++) {
#pragma unroll
            for (int e = 0; e < 4; e++) acc[i][j][e] = 0.f;
            accc[i][j][0] = 0u; accc[i][j][1] = 0u;
        }

    issue(0, 0);
    if (nk > 1) issue(1, 1);

    const int lr = lane & 15;
    const int lc = lane >> 4;

    for (int c = 0; c < nk; c++) {
        if (c == nk - 1) { CP_WAIT0(); } else { CP_WAIT1(); }
        __syncthreads();

        const uint32_t st  = smBase + (c & 1) * STAGE;
        const uint32_t aHi = st;
        const uint32_t aLo = st + TILE_A;
        const uint32_t wHi = st + 2 * TILE_A;
        const uint32_t wLo = st + 2 * TILE_A + TILE_W;

#pragma unroll
        for (int k16 = 0; k16 < 4; k16++) {
            const int cb = k16 * 32 + lc * 16;
            uint32_t bh[8], bl[8];
            {
                const uint32_t o0 = sw_off(wc * 32 + lr, cb);
                const uint32_t o1 = sw_off(wc * 32 + 16 + lr, cb);
                LDSM_X4(bh[0], bh[1], bh[2], bh[3], wHi + o0);
                LDSM_X4(bh[4], bh[5], bh[6], bh[7], wHi + o1);
                LDSM_X4(bl[0], bl[1], bl[2], bl[3], wLo + o0);
                LDSM_X4(bl[4], bl[5], bl[6], bl[7], wLo + o1);
            }
#pragma unroll
            for (int i = 0; i < 2; i++) {
                const uint32_t oA = sw_off(wr * 32 + i * 16 + lr, cb);
                uint32_t ah[4], al[4];
                LDSM_X4(ah[0], ah[1], ah[2], ah[3], aHi + oA);
                LDSM_X4(al[0], al[1], al[2], al[3], aLo + oA);
#pragma unroll
                for (int j = 0; j < 4; j++) {
                    const int jj = j >> 1, sel = j & 1;
                    const uint32_t b0h = bh[jj * 4 + sel], b1h = bh[jj * 4 + sel + 2];
                    const uint32_t b0l = bl[jj * 4 + sel], b1l = bl[jj * 4 + sel + 2];
                    mma_f32(acc[i][j],  ah, b0h, b1h);   // hi*hi  (f32 accum)
                    mma_f16(accc[i][j], al, b0h, b1h);   // lo*hi  (f16 accum)
                    mma_f16(accc[i][j], ah, b0l, b1l);   // hi*lo  (f16 accum)
                }
            }
        }

        if (c + 2 < nk) {
            __syncthreads();
            issue(c + 2, c & 1);
        }
    }

    // ---- epilogue ----
#pragma unroll
    for (int i = 0; i < 2; i++) {
        const int m0 = mBase + wr * 32 + i * 16 + (lane >> 2);
#pragma unroll
        for (int j = 0; j < 4; j++) {
            const int col = nBase + wc * 32 + j * 8 + 2 * (lane & 3);
            if (col < N) {
                const float2 c0 = __half22float2(*(__half2*)&accc[i][j][0]);
                const float2 c1 = __half22float2(*(__half2*)&accc[i][j][1]);
                float2 v0 = make_float2(acc[i][j][0] + c0.x * LO_INV,
                                        acc[i][j][1] + c0.y * LO_INV);
                float2 v1 = make_float2(acc[i][j][2] + c1.x * LO_INV,
                                        acc[i][j][3] + c1.y * LO_INV);
                if (EPI == 1) {
                    const float b0 = bias[col], b1 = bias[col + 1];
                    v0.x = softplus_f(v0.x + b0);
                    v0.y = softplus_f(v0.y + b1);
                    v1.x = softplus_f(v1.x + b0);
                    v1.y = softplus_f(v1.y + b1);
                }
                *(float2*)&C[(size_t)m0 * ldc + col] = v0;
                *(float2*)&C[(size_t)(m0 + 8) * ldc + col] = v1;
            }
        }
    }
}

// ---------------- causal depthwise conv (k=4) + bias + SiLU, fused fp16 split ----------------
#define CONV_LT 32
__global__ __launch_bounds__(256) void conv_silu_kernel(
    const float* __restrict__ cw, const float* __restrict__ cb)
{
    const int d  = blockIdx.x * 256 + threadIdx.x;
    const int b  = blockIdx.z;
    const int l0 = blockIdx.y * CONV_LT;

    const float w0 = cw[d * 4 + 0], w1 = cw[d * 4 + 1];
    const float w2 = cw[d * 4 + 2], w3 = cw[d * 4 + 3];
    const float bias = cb[d];

    const float* xp = g_xz + (size_t)b * LDIM * (2 * DINNER) + d;
    float xm3 = (l0 - 3 >= 0) ? xp[(size_t)(l0 - 3) * (2 * DINNER)] : 0.f;
    float xm2 = (l0 - 2 >= 0) ? xp[(size_t)(l0 - 2) * (2 * DINNER)] : 0.f;
    float xm1 = (l0 - 1 >= 0) ? xp[(size_t)(l0 - 1) * (2 * DINNER)] : 0.f;

    for (int l = l0; l < l0 + CONV_LT; l++) {
        const float xc = xp[(size_t)l * (2 * DINNER)];
        const float acc = bias + w0 * xm3 + w1 * xm2 + w2 * xm1 + w3 * xc;
        const float s = acc / (1.f + __expf(-acc));
        const size_t o = ((size_t)b * LDIM + l) * DINNER + d;
        g_xs[o] = s;
        __half h, lo;
        split_h(s, h, lo);
        g_xsh[o] = h;
        g_xsl[o] = lo;
        xm3 = xm2; xm2 = xm1; xm1 = xc;
    }
}

// ---------------- selective scan + D skip + SiLU(z) gate, fused fp16 split out ----------------
__global__ __launch_bounds__(128) void scan_kernel(
    const float* __restrict__ A_log, const float* __restrict__ Dvec)
{
    const int b    = blockIdx.y;
    const int tid  = threadIdx.x;
    const int sub  = tid & 3;
    const int dloc = tid >> 2;
    const int d    = blockIdx.x * 32 + dloc;
    const int n0   = sub * 4;

    __shared__ float Bsh[32][DSTATE];
    __shared__ float Csh[32][DSTATE];

    float a[4], h[4];
#pragma unroll
    for (int n = 0; n < 4; n++) {
        a[n] = -__expf(A_log[d * DSTATE + n0 + n]);
        h[n] = 0.f;
    }
    const float Dd = Dvec[d];
    const size_t rowBase = (size_t)b * LDIM;

    for (int t0 = 0; t0 < LDIM; t0 += 32) {
        __syncthreads();
        for (int i = tid; i < 32 * 32; i += 128) {
            const int tl = i >> 5;
            const int c  = i & 31;
            const float v = g_xdbl[(rowBase + t0 + tl) * XDBLW + DTRANK + c];
            if (c < DSTATE) Bsh[tl][c] = v;
            else            Csh[tl][c - DSTATE] = v;
        }
        __syncthreads();

#pragma unroll 4
        for (int tl = 0; tl < 32; tl++) {
            const size_t r = rowBase + t0 + tl;
            const float dt = g_dt[r * DINNER + d];
            const float x  = g_xs[r * DINNER + d];
            const float z  = g_xz[r * (2 * DINNER) + DINNER + d];
            const float dtx = dt * x;
            float y = 0.f;
#pragma unroll
            for (int n = 0; n < 4; n++) {
                const float dA = __expf(dt * a[n]);
                h[n] = h[n] * dA + dtx * Bsh[tl][n0 + n];
                y += h[n] * Csh[tl][n0 + n];
            }
            y += __shfl_xor_sync(0xffffffffu, y, 1);
            y += __shfl_xor_sync(0xffffffffu, y, 2);
            y += Dd * x;
            const float sz = z / (1.f + __expf(-z));
            if (sub == 0) {
                const float yv = y * sz;
                __half hh, ll;
                split_h(yv, hh, ll);
                g_yh[r * DINNER + d] = hh;
                g_yl[r * DINNER + d] = ll;
            }
        }
    }
}

// ---------------- launch ----------------
extern "C" void kernel_launch(void* const* d_in, const int* in_sizes, int n_in,
                              void* d_out, int out_size)
{
    const float* x       = (const float*)d_in[0];
    const float* W_in    = (const float*)d_in[1];
    const float* conv_w  = (const float*)d_in[2];
    const float* conv_b  = (const float*)d_in[3];
    const float* W_xproj = (const float*)d_in[4];
    const float* W_dt    = (const float*)d_in[5];
    const float* b_dt    = (const float*)d_in[6];
    const float* A_log   = (const float*)d_in[7];
    const float* Dvec    = (const float*)d_in[8];
    const float* W_out   = (const float*)d_in[9];
    float* out = (float*)d_out;

    float *xz, *xdbl, *dtb;
    cudaGetSymbolAddress((void**)&xz,   g_xz);
    cudaGetSymbolAddress((void**)&xdbl, g_xdbl);
    cudaGetSymbolAddress((void**)&dtb,  g_dt);

    __half *xh, *xl, *wih, *wil, *xsh, *xsl, *wxh, *wxl;
    __half *dah, *dal, *wdh, *wdl, *yh, *yl, *woh, *wol;
    cudaGetSymbolAddress((void**)&xh,  g_xh);  cudaGetSymbolAddress((void**)&xl,  g_xl);
    cudaGetSymbolAddress((void**)&wih, g_wih); cudaGetSymbolAddress((void**)&wil, g_wil);
    cudaGetSymbolAddress((void**)&xsh, g_xsh); cudaGetSymbolAddress((void**)&xsl, g_xsl);
    cudaGetSymbolAddress((void**)&wxh, g_wxh); cudaGetSymbolAddress((void**)&wxl, g_wxl);
    cudaGetSymbolAddress((void**)&dah, g_dah); cudaGetSymbolAddress((void**)&dal, g_dal);
    cudaGetSymbolAddress((void**)&wdh, g_wdh); cudaGetSymbolAddress((void**)&wdl, g_wdl);
    cudaGetSymbolAddress((void**)&yh,  g_yh);  cudaGetSymbolAddress((void**)&yl,  g_yl);
    cudaGetSymbolAddress((void**)&woh, g_woh); cudaGetSymbolAddress((void**)&wol, g_wol);

    constexpr int SMEM = 2 * (2 * 128 * 128 + 2 * 64 * 128);  // 98304 B
    cudaFuncSetAttribute((const void*)gemm_mma2<0>,
                         cudaFuncAttributeMaxDynamicSharedMemorySize, SMEM);
    cudaFuncSetAttribute((const void*)gemm_mma2<1>,
                         cudaFuncAttributeMaxDynamicSharedMemorySize, SMEM);

    // ---- packs for in_proj ----
    {
        int t8 = NROWS * DMODEL / 8;
        pack_plain<<<(t8 + 255) / 256, 256>>>(x, DMODEL, DMODEL, xh, xl, t8);
        t8 = 2 * DINNER * DMODEL / 8;
        pack_plain<<<(t8 + 255) / 256, 256>>>(W_in, DMODEL, DMODEL, wih, wil, t8);
    }

    // 1. in_proj: xz = x @ W_in^T  (M=4096, N=4096, K=1024)
    gemm_mma2<0><<<dim3(4096 / 64, 32), 256, SMEM>>>(
        xh, xl, wih, wil, xz, 2 * DINNER, 2 * DINNER, DMODEL, nullptr);

    // 2. conv + SiLU (+ fp16 split of xs)
    conv_silu_kernel<<<dim3(DINNER / 256, LDIM / CONV_LT, BDIM), 256>>>(conv_w, conv_b);

    // ---- pack W_xproj ----
    {
        int t8 = XDBLW * DINNER / 8;
        pack_plain<<<(t8 + 255) / 256, 256>>>(W_xproj, DINNER, DINNER, wxh, wxl, t8);
    }

    // 3. x_proj: x_dbl = xs @ W_xproj^T  (M=4096, N=96, K=2048)
    gemm_mma2<0><<<dim3(2, 32), 256, SMEM>>>(
        xsh, xsl, wxh, wxl, xdbl, XDBLW, XDBLW, DINNER, nullptr);

    // ---- packs for dt gemm ----
    {
        int t8 = NROWS * DTRANK / 8;
        pack_plain<<<(t8 + 255) / 256, 256>>>(xdbl, XDBLW, DTRANK, dah, dal, t8);
        t8 = DINNER * DTRANK / 8;
        pack_plain<<<(t8 + 255) / 256, 256>>>(W_dt, DTRANK, DTRANK, wdh, wdl, t8);
    }

    // 4. dt = softplus(x_dbl[:, :64] @ W_dt^T + b_dt)  (M=4096, N=2048, K=64)
    gemm_mma2<1><<<dim3(DINNER / 64, 32), 256, SMEM>>>(
        dah, dal, wdh, wdl, dtb, DINNER, DINNER, DTRANK, b_dt);

    // 5. selective scan + D skip + gate (+ fp16 split of y)
    scan_kernel<<<dim3(DINNER / 32, BDIM), 128>>>(A_log, Dvec);

    // ---- pack W_out ----
    {
        int t8 = DMODEL * DINNER / 8;
        pack_plain<<<(t8 + 255) / 256, 256>>>(W_out, DINNER, DINNER, woh, wol, t8);
    }

    // 6. out_proj: out = y @ W_out^T  (M=4096, N=1024, K=2048)
    gemm_mma2<0><<<dim3(DMODEL / 64, 32), 256, SMEM>>>(
        yh, yl, woh, wol, out, DMODEL, DMODEL, DINNER, nullptr);
}